// round 1
// baseline (speedup 1.0000x reference)
#include <cuda_runtime.h>
#include <math.h>

#define NN 4
#define LL 4096
#define HH 16
#define DD 64
#define MM 64
#define CC 128
#define GG 32          // LL / CC
#define EPSF 1e-6f

// Scratch (allocation-free per harness rules): per-chunk KV states + k-sums.
// Overwritten in place by the prefix kernel each launch (deterministic).
static __device__ float g_kv[(size_t)NN * GG * HH * DD * MM];   // 33.5 MB
static __device__ float g_ksum[(size_t)NN * GG * HH * DD];

__device__ __forceinline__ float phi(float x) {
    // elu(x) + 1 : x>0 -> x+1 ; x<=0 -> exp(x)
    return x > 0.f ? x + 1.f : __expf(x);
}

// ---------------------------------------------------------------------------
// Kernel A: per-chunk KV state kv[d][m] = sum_c phi(k)[c][d] * v[c][m]
//           and ksum[d] = sum_c phi(k)[c][d]
// grid = N*G*H (2048), block = 256, dyn smem = 2*128*65*4 = 66560 B
// ---------------------------------------------------------------------------
__global__ void __launch_bounds__(256) chunk_state_kernel(
    const float* __restrict__ k, const float* __restrict__ v)
{
    extern __shared__ float sm[];
    float* sk = sm;              // [CC][65]
    float* sv = sm + CC * 65;    // [CC][65]

    int bid = blockIdx.x;
    int h = bid % HH;
    int g = (bid / HH) % GG;
    int n = bid / (HH * GG);
    size_t base = (((size_t)n * LL + (size_t)g * CC) * HH + h) * DD;
    int tid = threadIdx.x;

    // Load 128 rows x 64 floats (float4), apply phi to k
    for (int i = tid; i < CC * (DD / 4); i += 256) {
        int c = i >> 4;
        int dv = (i & 15) << 2;
        size_t off = base + (size_t)c * HH * DD + dv;
        float4 k4 = *(const float4*)(k + off);
        float4 v4 = *(const float4*)(v + off);
        sk[c * 65 + dv + 0] = phi(k4.x);
        sk[c * 65 + dv + 1] = phi(k4.y);
        sk[c * 65 + dv + 2] = phi(k4.z);
        sk[c * 65 + dv + 3] = phi(k4.w);
        sv[c * 65 + dv + 0] = v4.x;
        sv[c * 65 + dv + 1] = v4.y;
        sv[c * 65 + dv + 2] = v4.z;
        sv[c * 65 + dv + 3] = v4.w;
    }
    __syncthreads();

    int ty = tid >> 4, tx = tid & 15;
    int d0 = ty * 4, m0 = tx * 4;
    float acc[4][4] = {};
#pragma unroll 4
    for (int c = 0; c < CC; c++) {
        float a[4], b[4];
#pragma unroll
        for (int i = 0; i < 4; i++) a[i] = sk[c * 65 + d0 + i];
#pragma unroll
        for (int j = 0; j < 4; j++) b[j] = sv[c * 65 + m0 + j];
#pragma unroll
        for (int i = 0; i < 4; i++)
#pragma unroll
            for (int j = 0; j < 4; j++)
                acc[i][j] = fmaf(a[i], b[j], acc[i][j]);
    }

    float* kvout = g_kv + (size_t)bid * DD * MM;
#pragma unroll
    for (int i = 0; i < 4; i++) {
        float4 r = make_float4(acc[i][0], acc[i][1], acc[i][2], acc[i][3]);
        *(float4*)(kvout + (size_t)(d0 + i) * MM + m0) = r;
    }

    if (tid < DD) {
        float s = 0.f;
        for (int c = 0; c < CC; c++) s += sk[c * 65 + tid];
        g_ksum[(size_t)bid * DD + tid] = s;
    }
}

// ---------------------------------------------------------------------------
// Kernel B: exclusive prefix over chunks (axis g) for kv and ksum, in place.
// grid = N*H (64), block = 256
// ---------------------------------------------------------------------------
__global__ void __launch_bounds__(256) prefix_kernel()
{
    int nh = blockIdx.x;           // 0..63
    int n = nh / HH, h = nh % HH;
    for (int pos = threadIdx.x; pos < DD * MM; pos += 256) {
        float run = 0.f;
        for (int g = 0; g < GG; g++) {
            size_t idx = (((size_t)(n * GG + g) * HH) + h) * (DD * MM) + pos;
            float t = g_kv[idx];
            g_kv[idx] = run;
            run += t;
        }
    }
    if (threadIdx.x < DD) {
        float run = 0.f;
        for (int g = 0; g < GG; g++) {
            size_t idx = (((size_t)(n * GG + g) * HH) + h) * DD + threadIdx.x;
            float t = g_ksum[idx];
            g_ksum[idx] = run;
            run += t;
        }
    }
}

// ---------------------------------------------------------------------------
// Kernel C: per (n,g,h) block:
//   scores = tril(phi(q) @ phi(k)^T)         [128x128]
//   z[l]   = rowsum(scores)[l] + phi(q)[l] . ksum_prev + eps
//   out    = (scores @ v + phi(q) @ kv_prev) / z
// grid = N*G*H (2048), block = 256, dyn smem = 183296 B
// ---------------------------------------------------------------------------
__global__ void __launch_bounds__(256) output_kernel(
    const float* __restrict__ q, const float* __restrict__ k,
    const float* __restrict__ v, float* __restrict__ out)
{
    extern __shared__ float sm[];
    float* sq  = sm;                 // [128][65]
    float* sk  = sq  + CC * 65;      // [128][65]
    float* sv  = sk  + CC * 65;      // [128][65]
    float* skv = sv  + CC * 65;      // [64][65]
    float* sks = skv + DD * 65;      // [64]
    float* sz  = sks + DD;           // [128]
    float* ss  = sz  + CC;           // [128][129]

    int bid = blockIdx.x;
    int h = bid % HH;
    int g = (bid / HH) % GG;
    int n = bid / (HH * GG);
    size_t base = (((size_t)n * LL + (size_t)g * CC) * HH + h) * DD;
    int tid = threadIdx.x;

    // Load q,k (phi) and v tiles
    for (int i = tid; i < CC * (DD / 4); i += 256) {
        int c = i >> 4;
        int dv = (i & 15) << 2;
        size_t off = base + (size_t)c * HH * DD + dv;
        float4 q4 = *(const float4*)(q + off);
        float4 k4 = *(const float4*)(k + off);
        float4 v4 = *(const float4*)(v + off);
        sq[c * 65 + dv + 0] = phi(q4.x);
        sq[c * 65 + dv + 1] = phi(q4.y);
        sq[c * 65 + dv + 2] = phi(q4.z);
        sq[c * 65 + dv + 3] = phi(q4.w);
        sk[c * 65 + dv + 0] = phi(k4.x);
        sk[c * 65 + dv + 1] = phi(k4.y);
        sk[c * 65 + dv + 2] = phi(k4.z);
        sk[c * 65 + dv + 3] = phi(k4.w);
        sv[c * 65 + dv + 0] = v4.x;
        sv[c * 65 + dv + 1] = v4.y;
        sv[c * 65 + dv + 2] = v4.z;
        sv[c * 65 + dv + 3] = v4.w;
    }
    // Load kv_prev (exclusive prefix state) and ksum_prev
    {
        const float* kvp = g_kv + (size_t)bid * DD * MM;
        for (int i = tid; i < (DD * MM) / 4; i += 256) {
            int d = i >> 4;
            int mv = (i & 15) << 2;
            float4 t = *(const float4*)(kvp + (size_t)d * MM + mv);
            skv[d * 65 + mv + 0] = t.x;
            skv[d * 65 + mv + 1] = t.y;
            skv[d * 65 + mv + 2] = t.z;
            skv[d * 65 + mv + 3] = t.w;
        }
        if (tid < DD) sks[tid] = g_ksum[(size_t)bid * DD + tid];
    }
    __syncthreads();

    // Warp-swizzled thread->tile mapping (reduces LDS bank conflicts)
    int lane = tid & 31, w = tid >> 5;
    int wy = w >> 1, wx = w & 1;       // warps: 4 row-groups x 2 col-groups
    int ly = lane >> 3, lx = lane & 7; // lanes: 4 x 8
    int r0 = (wy * 4 + ly) * 8;        // 8 output rows per thread
    int cg = wx * 8 + lx;              // 0..15
    int c0 = cg * 8;                   // scores: 8 cols per thread
    int m0 = cg * 4;                   // output: 4 cols per thread

    // ---- Phase 1: masked scores ----
    float acc[8][8];
#pragma unroll
    for (int i = 0; i < 8; i++)
#pragma unroll
        for (int j = 0; j < 8; j++) acc[i][j] = 0.f;

    if (c0 <= r0 + 7) {  // skip tiles strictly above the diagonal
#pragma unroll 4
        for (int d = 0; d < DD; d++) {
            float a[8], b[8];
#pragma unroll
            for (int i = 0; i < 8; i++) a[i] = sq[(r0 + i) * 65 + d];
#pragma unroll
            for (int j = 0; j < 8; j++) b[j] = sk[(c0 + j) * 65 + d];
#pragma unroll
            for (int i = 0; i < 8; i++)
#pragma unroll
                for (int j = 0; j < 8; j++)
                    acc[i][j] = fmaf(a[i], b[j], acc[i][j]);
        }
    }
#pragma unroll
    for (int i = 0; i < 8; i++)
#pragma unroll
        for (int j = 0; j < 8; j++) {
            int r = r0 + i, c = c0 + j;
            ss[r * 129 + c] = (c <= r) ? acc[i][j] : 0.f;
        }
    __syncthreads();

    // ---- Phase 2: normalizer z ----
    if (tid < CC) {
        float s = EPSF;
#pragma unroll 4
        for (int c = 0; c < CC; c++) s += ss[tid * 129 + c];
#pragma unroll 4
        for (int d = 0; d < DD; d++) s = fmaf(sq[tid * 65 + d], sks[d], s);
        sz[tid] = s;
    }
    __syncthreads();

    // ---- Phase 3: out = scores @ v + q @ kv_prev, normalized ----
    float o[8][4];
#pragma unroll
    for (int i = 0; i < 8; i++)
#pragma unroll
        for (int j = 0; j < 4; j++) o[i][j] = 0.f;

    int kmax = r0 + 8;  // scores row r has zeros beyond column r
#pragma unroll 2
    for (int kk = 0; kk < kmax; kk++) {
        float a[8], b[4];
#pragma unroll
        for (int i = 0; i < 8; i++) a[i] = ss[(r0 + i) * 129 + kk];
#pragma unroll
        for (int j = 0; j < 4; j++) b[j] = sv[kk * 65 + m0 + j];
#pragma unroll
        for (int i = 0; i < 8; i++)
#pragma unroll
            for (int j = 0; j < 4; j++)
                o[i][j] = fmaf(a[i], b[j], o[i][j]);
    }
#pragma unroll 2
    for (int d = 0; d < DD; d++) {
        float a[8], b[4];
#pragma unroll
        for (int i = 0; i < 8; i++) a[i] = sq[(r0 + i) * 65 + d];
#pragma unroll
        for (int j = 0; j < 4; j++) b[j] = skv[d * 65 + m0 + j];
#pragma unroll
        for (int i = 0; i < 8; i++)
#pragma unroll
            for (int j = 0; j < 4; j++)
                o[i][j] = fmaf(a[i], b[j], o[i][j]);
    }

#pragma unroll
    for (int i = 0; i < 8; i++) {
        int l = g * CC + r0 + i;
        float rz = 1.0f / sz[r0 + i];
        float4 res = make_float4(o[i][0] * rz, o[i][1] * rz,
                                 o[i][2] * rz, o[i][3] * rz);
        *(float4*)(out + (((size_t)n * LL + l) * HH + h) * MM + m0) = res;
    }
}

// ---------------------------------------------------------------------------
extern "C" void kernel_launch(void* const* d_in, const int* in_sizes, int n_in,
                              void* d_out, int out_size)
{
    const float* q = (const float*)d_in[0];
    const float* k = (const float*)d_in[1];
    const float* v = (const float*)d_in[2];
    float* out = (float*)d_out;

    const int SMEM_A = 2 * CC * 65 * (int)sizeof(float);                      // 66560
    const int SMEM_C = (3 * CC * 65 + DD * 65 + DD + CC + CC * 129)
                       * (int)sizeof(float);                                  // 183296

    cudaFuncSetAttribute(chunk_state_kernel,
                         cudaFuncAttributeMaxDynamicSharedMemorySize, SMEM_A);
    cudaFuncSetAttribute(output_kernel,
                         cudaFuncAttributeMaxDynamicSharedMemorySize, SMEM_C);

    chunk_state_kernel<<<NN * GG * HH, 256, SMEM_A>>>(k, v);
    prefix_kernel<<<NN * HH, 256>>>();
    output_kernel<<<NN * GG * HH, 256, SMEM_C>>>(q, k, v, out);
}